// round 12
// baseline (speedup 1.0000x reference)
#include <cuda_runtime.h>
#include <cuda_bf16.h>
#include <math.h>
#include <stdint.h>

// Shapes (fixed by the problem)
#define BB     512
#define NSLOT  128
#define IN_    2048
#define MEM_   64
#define OUT_   2048
#define KTOT   2176   // IN + 2*MEM
#define NK1    16     // split-K factor for K1
#define NCOLS  130    // 64 (q) + 65 (xr) + 1 (xf)

// -------------------- device scratch (no allocations allowed) ----------------
__device__ float g_kpart[NK1 * BB * NCOLS];   // K1 partial sums
__device__ float g_wpack[IN_ * NCOLS];        // packed [W_ar | W_r_x | W_f_x]
__device__ float g_ar[BB * MEM_];             // active recall
__device__ float g_pr[BB * MEM_];             // passive recall

// bf16 split operands for tensor-core K3
__device__ __nv_bfloat16 g_ahi[BB * KTOT];      // A = [x | ar | pr] hi
__device__ __nv_bfloat16 g_alo[BB * KTOT];      // A lo
__device__ __nv_bfloat16 g_bhi[OUT_ * KTOT];    // W_o^T hi  (N-major rows, K contiguous)
__device__ __nv_bfloat16 g_blo[OUT_ * KTOT];    // W_o^T lo

// ============================================================================
// PTX helpers (base compute_103 compatible: ldmatrix / mma.sync / cp.async)
// ============================================================================
__device__ __forceinline__ uint32_t smem_u32(const void* p) {
    uint32_t a;
    asm("{ .reg .u64 t; cvta.to.shared.u64 t, %1; cvt.u32.u64 %0, t; }" : "=r"(a) : "l"(p));
    return a;
}

__device__ __forceinline__ void ldsm4(uint32_t* r, uint32_t addr) {
    asm volatile("ldmatrix.sync.aligned.m8n8.x4.shared.b16 {%0,%1,%2,%3}, [%4];"
        : "=r"(r[0]), "=r"(r[1]), "=r"(r[2]), "=r"(r[3]) : "r"(addr));
}

__device__ __forceinline__ void mma16816(float* d, const uint32_t* a, const uint32_t* b) {
    asm volatile("mma.sync.aligned.m16n8k16.row.col.f32.bf16.bf16.f32 "
        "{%0,%1,%2,%3}, {%4,%5,%6,%7}, {%8,%9}, {%0,%1,%2,%3};"
        : "+f"(d[0]), "+f"(d[1]), "+f"(d[2]), "+f"(d[3])
        : "r"(a[0]), "r"(a[1]), "r"(a[2]), "r"(a[3]), "r"(b[0]), "r"(b[1]));
}

__device__ __forceinline__ void cpasync16(uint32_t smem, const void* g) {
    asm volatile("cp.async.cg.shared.global [%0], [%1], 16;" :: "r"(smem), "l"(g));
}
#define CP_COMMIT() asm volatile("cp.async.commit_group;" ::: "memory")
#define CP_WAIT1()  asm volatile("cp.async.wait_group 1;" ::: "memory")
#define CP_WAIT0()  asm volatile("cp.async.wait_group 0;" ::: "memory")

// ============================================================================
// K0: pack the x-side weight columns into one contiguous [2048 x 130] matrix
// ============================================================================
__global__ void pack_kernel(const float* __restrict__ W_ar,
                            const float* __restrict__ W_r,
                            const float* __restrict__ W_f) {
    int idx = blockIdx.x * 256 + threadIdx.x;
    if (idx >= IN_ * NCOLS) return;
    int k = idx / NCOLS;
    int j = idx - k * NCOLS;
    float w;
    if (j < 64)       w = W_ar[k * 64 + j];
    else if (j < 129) w = W_r[k * 65 + (j - 64)];
    else              w = W_f[k];
    g_wpack[idx] = w;
}

// ============================================================================
// K1 v2: partial GEMM  x[512,2048] @ wpack[2048,130] -> g_kpart[16][512][130]
//        grid (16 m-tiles, 16 k-tiles), 256 threads, 16 rows/thread (ILP 16)
// ============================================================================
__global__ void __launch_bounds__(256) k1_kernel(const float* __restrict__ x) {
    const int mb = blockIdx.x;
    const int kb = blockIdx.y;
    const int t  = threadIdx.x;
    __shared__ float xs[32][128];

    for (int i = t; i < 1024; i += 256) {
        int m = i >> 5, c = (i & 31) * 4;
        *(float4*)&xs[m][c] = *(const float4*)&x[(mb * 32 + m) * IN_ + kb * 128 + c];
    }
    __syncthreads();

    const int mh = t >> 7;       // 0/1 -> rows mh*16 .. mh*16+15
    const int j0 = t & 127;
    for (int j = j0; j < NCOLS; j += 128) {
        float acc[16];
#pragma unroll
        for (int m = 0; m < 16; m++) acc[m] = 0.f;
        const float* wp = g_wpack + (kb * 128) * NCOLS + j;
#pragma unroll 8
        for (int k = 0; k < 128; k++) {
            float w = wp[k * NCOLS];
#pragma unroll
            for (int m = 0; m < 16; m++) acc[m] = fmaf(xs[mh * 16 + m][k], w, acc[m]);
        }
        float* outp = g_kpart + (kb * BB + mb * 32 + mh * 16) * NCOLS + j;
#pragma unroll
        for (int m = 0; m < 16; m++) outp[m * NCOLS] = acc[m];
    }
}

// ============================================================================
// K2 v2: per-batch fused attention/softmax/recalls + gated memory update.
//        256 threads, shuffle reductions, pair-split update loops.
// ============================================================================
#define K2_SMEM ((NSLOT * 65 + 64 * 68) * 4)   // 50688 bytes dynamic

__global__ void __launch_bounds__(256) k2_kernel(
        const float* __restrict__ memory,
        const float* __restrict__ b_ar,
        const float* __restrict__ W_pr,
        const float* __restrict__ b_pr,
        const float* __restrict__ W_f,
        const float* __restrict__ b_f,
        const float* __restrict__ W_r,
        const float* __restrict__ b_r,
        float* __restrict__ new_memory) {
    extern __shared__ float dyn[];
    float* mem_s = dyn;                       // [128][65]
    float* wrm   = dyn + NSLOT * 65;          // [64][68]

    __shared__ float sq[64];
    __shared__ float sxr[65];
    __shared__ float swfm[64];
    __shared__ float swpr[64];
    __shared__ float sscore[128];
    __shared__ float sp[128];
    __shared__ float red[256];
    __shared__ float wred[4][8];
    __shared__ float sxf;

    const int b    = blockIdx.x;
    const int t    = threadIdx.x;
    const int lane = t & 31;
    const int wid  = t >> 5;

    // ---- reduce K1 split-K partials, add biases (130 cols, one pass) ----
    if (t < NCOLS) {
        float s = 0.f;
#pragma unroll
        for (int kb = 0; kb < NK1; kb++) s += g_kpart[(kb * BB + b) * NCOLS + t];
        if (t < 64)       sq[t] = s + b_ar[t];
        else if (t < 129) sxr[t - 64] = s + b_r[t - 64];
        else              sxf = s + b_f[0];
    }

    // ---- stage weights ----
    for (int i = t; i < 64 * 68; i += 256) {
        int k = i / 68, c = i - k * 68;
        wrm[i] = (c < 65) ? W_r[IN_ * 65 + k * 65 + c] : 0.f;
    }
    if (t < 64) { swfm[t] = W_f[IN_ + t]; swpr[t] = W_pr[t]; }

    // ---- stage memory[b] (float4 loads, padded stride-65 rows) ----
    const float4* m4 = (const float4*)(memory + (size_t)b * (NSLOT * MEM_));
    for (int i = t; i < 2048; i += 256) {
        int row = i >> 4, c4 = (i & 15) * 4;
        float4 v = m4[i];
        float* d = &mem_s[row * 65 + c4];
        d[0] = v.x; d[1] = v.y; d[2] = v.z; d[3] = v.w;
    }
    __syncthreads();                                          // (1)

    // ---- per-slot logits (threads 0..127) ----
    float sc = 0.f, pl = 0.f;
    if (t < 128) {
        const float* my = mem_s + t * 65;
#pragma unroll
        for (int k = 0; k < 64; k++) {
            float mv = my[k];
            sc = fmaf(mv, sq[k], sc);
            pl = fmaf(mv, swpr[k], pl);
        }
        pl += b_pr[0];
    }

    // ---- softmax 1 (active): max then sum, shuffle + 8-way combine ----
    float v = (t < 128) ? sc : -INFINITY;
#pragma unroll
    for (int o = 16; o > 0; o >>= 1) v = fmaxf(v, __shfl_xor_sync(0xFFFFFFFFu, v, o));
    if (lane == 0) wred[0][wid] = v;
    __syncthreads();                                          // (2)
    float mx = wred[0][0];
#pragma unroll
    for (int w = 1; w < 8; w++) mx = fmaxf(mx, wred[0][w]);
    float e1 = (t < 128) ? expf(sc - mx) : 0.f;
    v = e1;
#pragma unroll
    for (int o = 16; o > 0; o >>= 1) v += __shfl_xor_sync(0xFFFFFFFFu, v, o);
    if (lane == 0) wred[1][wid] = v;
    __syncthreads();                                          // (3)
    float s1 = wred[1][0] + wred[1][1] + wred[1][2] + wred[1][3]
             + wred[1][4] + wred[1][5] + wred[1][6] + wred[1][7];
    if (t < 128) sscore[t] = e1 / s1;

    // ---- softmax 2 (passive) ----
    v = (t < 128) ? pl : -INFINITY;
#pragma unroll
    for (int o = 16; o > 0; o >>= 1) v = fmaxf(v, __shfl_xor_sync(0xFFFFFFFFu, v, o));
    if (lane == 0) wred[2][wid] = v;
    __syncthreads();                                          // (4)
    float mx2 = wred[2][0];
#pragma unroll
    for (int w = 1; w < 8; w++) mx2 = fmaxf(mx2, wred[2][w]);
    float e2 = (t < 128) ? expf(pl - mx2) : 0.f;
    v = e2;
#pragma unroll
    for (int o = 16; o > 0; o >>= 1) v += __shfl_xor_sync(0xFFFFFFFFu, v, o);
    if (lane == 0) wred[3][wid] = v;
    __syncthreads();                                          // (5)
    float s2 = wred[3][0] + wred[3][1] + wred[3][2] + wred[3][3]
             + wred[3][4] + wred[3][5] + wred[3][6] + wred[3][7];
    if (t < 128) sp[t] = e2 / s2;
    __syncthreads();                                          // (6)

    // ---- active / passive recall: col = t&63, 4-way row split ----
    {
        const int c = t & 63;
        const int h = t >> 6;               // 0..3 -> rows h*32..h*32+31
        float a = 0.f, p = 0.f;
#pragma unroll 4
        for (int n = h * 32; n < h * 32 + 32; n++) {
            float mv = mem_s[n * 65 + c];
            a = fmaf(mv, sscore[n], a);
            p = fmaf(mv, sp[n], p);
        }
        red[t] = a;
        __syncthreads();                                      // (7)
        if (t < 64) g_ar[b * 64 + t] = red[t] + red[t + 64] + red[t + 128] + red[t + 192];
        __syncthreads();                                      // (8)
        red[t] = p;
        __syncthreads();                                      // (9)
        if (t < 64) g_pr[b * 64 + t] = red[t] + red[t + 64] + red[t + 128] + red[t + 192];
    }

    // ---- gated memory update: slot s = t>>1, k-half h = t&1 ----
    const int s  = t >> 1;
    const int h  = t & 1;
    const int kb0 = h * 32;
    float mreg[32];
#pragma unroll
    for (int k = 0; k < 32; k++) mreg[k] = mem_s[s * 65 + kb0 + k];

    float fl = 0.f;
#pragma unroll
    for (int k = 0; k < 32; k++) fl = fmaf(mreg[k], swfm[kb0 + k], fl);
    fl += __shfl_xor_sync(0xFFFFFFFFu, fl, 1);
    fl += sxf;
    const float fgt = 1.1f / (1.f + expf(-fl));

    float r64 = 0.f;
#pragma unroll
    for (int k = 0; k < 32; k++) r64 = fmaf(mreg[k], wrm[(kb0 + k) * 68 + 64], r64);
    r64 += __shfl_xor_sync(0xFFFFFFFFu, r64, 1);
    r64 += sxr[64];

#pragma unroll 4
    for (int jb = 0; jb < 16; jb++) {
        float a0 = 0.f, a1 = 0.f, a2 = 0.f, a3 = 0.f;
#pragma unroll
        for (int k = 0; k < 32; k++) {
            float4 w = *(const float4*)&wrm[(kb0 + k) * 68 + jb * 4];
            float mv = mreg[k];
            a0 = fmaf(mv, w.x, a0);
            a1 = fmaf(mv, w.y, a1);
            a2 = fmaf(mv, w.z, a2);
            a3 = fmaf(mv, w.w, a3);
        }
        a0 += __shfl_xor_sync(0xFFFFFFFFu, a0, 1);
        a1 += __shfl_xor_sync(0xFFFFFFFFu, a1, 1);
        a2 += __shfl_xor_sync(0xFFFFFFFFu, a2, 1);
        a3 += __shfl_xor_sync(0xFFFFFFFFu, a3, 1);
        // thread h writes columns jb*4 + 2h, jb*4 + 2h + 1
        const int idx = jb * 4 + 2 * h;
        float aq0 = (h ? a2 : a0) + sxr[idx];
        float aq1 = (h ? a3 : a1) + sxr[idx + 1];
        float m0 = mem_s[s * 65 + idx];
        float m1 = mem_s[s * 65 + idx + 1];
        mem_s[s * 65 + idx]     = fmaf(m0, fgt, r64 * aq0);
        mem_s[s * 65 + idx + 1] = fmaf(m1, fgt, r64 * aq1);
    }
    __syncthreads();                                          // (10)

    // ---- writeback (float4) ----
    float4* orow = (float4*)(new_memory + (size_t)b * (NSLOT * MEM_));
    for (int i = t; i < 2048; i += 256) {
        int row = i >> 4, c4 = (i & 15) * 4;
        const float* sptr = &mem_s[row * 65 + c4];
        float4 v4;
        v4.x = sptr[0]; v4.y = sptr[1]; v4.z = sptr[2]; v4.w = sptr[3];
        orow[i] = v4;
    }
}

// ============================================================================
// convA: build bf16 hi/lo of A = [x | ar | pr]  (512 x 2176)
// ============================================================================
__global__ void convA_kernel(const float* __restrict__ x) {
    int i = blockIdx.x * 256 + threadIdx.x;
    if (i >= BB * KTOT) return;
    int m = i / KTOT, k = i - m * KTOT;
    float v;
    if (k < IN_)              v = x[m * IN_ + k];
    else if (k < IN_ + MEM_)  v = g_ar[m * MEM_ + (k - IN_)];
    else                      v = g_pr[m * MEM_ + (k - IN_ - MEM_)];
    __nv_bfloat16 h = __float2bfloat16(v);
    g_ahi[i] = h;
    g_alo[i] = __float2bfloat16(v - __bfloat162float(h));
}

// ============================================================================
// convB v2: transpose + bf16 split of W_o with packed uint32 stores.
//           block tile: 64 k rows x 32 n cols.  grid (64, 34), 256 threads.
// ============================================================================
__global__ void __launch_bounds__(256) convB_kernel(const float* __restrict__ W_o) {
    __shared__ float tsm[64][33];
    const int nb = blockIdx.x;   // 64 n-tiles of 32
    const int kb = blockIdx.y;   // 34 k-tiles of 64
    const int tx = threadIdx.x & 31, ty = threadIdx.x >> 5;

    for (int r = ty; r < 64; r += 8)
        tsm[r][tx] = W_o[(size_t)(kb * 64 + r) * OUT_ + nb * 32 + tx];
    __syncthreads();

#pragma unroll
    for (int it = 0; it < 4; it++) {
        int n  = it * 8 + ty;   // 0..31 (local n)
        int kp = tx;            // 0..31 (k pair)
        float v0 = tsm[kp * 2][n];
        float v1 = tsm[kp * 2 + 1][n];
        __nv_bfloat16 h0 = __float2bfloat16(v0);
        __nv_bfloat16 h1 = __float2bfloat16(v1);
        __nv_bfloat16 l0 = __float2bfloat16(v0 - __bfloat162float(h0));
        __nv_bfloat16 l1 = __float2bfloat16(v1 - __bfloat162float(h1));
        uint32_t uh = ((uint32_t)__bfloat16_as_ushort(h1) << 16) | __bfloat16_as_ushort(h0);
        uint32_t ul = ((uint32_t)__bfloat16_as_ushort(l1) << 16) | __bfloat16_as_ushort(l0);
        size_t o2 = ((size_t)(nb * 32 + n) * KTOT + kb * 64) / 2 + kp;
        ((uint32_t*)g_bhi)[o2] = uh;
        ((uint32_t*)g_blo)[o2] = ul;
    }
}

// ============================================================================
// K3: mma.sync bf16 3-split GEMM  D[512,2048] = A[512,2176] @ W_o + b_o
//     CTA tile 64(M) x 128(N), BK=32, 8 warps (warp tile 32x32),
//     cp.async double-buffered SMEM (rows padded to 80B: conflict-free LDSM).
// ============================================================================
#define BM     64
#define BN     128
#define BK     32
#define ROWB   80                       // 64B data + 16B pad per BK row
#define OFF_AHI 0
#define OFF_ALO (BM * ROWB)             // 5120
#define OFF_BHI (2 * BM * ROWB)         // 10240
#define OFF_BLO (OFF_BHI + BN * ROWB)   // 20480
#define STAGE_B (OFF_BLO + BN * ROWB)   // 30720
#define NKT    (KTOT / BK)              // 68
#define K3_SMEM (2 * STAGE_B + 512)

__device__ __forceinline__ void load_stage(uint32_t sbase, int row0, int col0,
                                           int kcol, int tid) {
    const int r = tid >> 2, c = tid & 3;
    {
        size_t gi = (size_t)(row0 + r) * KTOT + kcol + c * 8;
        cpasync16(sbase + OFF_AHI + r * ROWB + c * 16, g_ahi + gi);
        cpasync16(sbase + OFF_ALO + r * ROWB + c * 16, g_alo + gi);
    }
#pragma unroll
    for (int it = 0; it < 2; it++) {
        int i = tid + it * 256;
        int rb = i >> 2, cb = i & 3;
        size_t gi = (size_t)(col0 + rb) * KTOT + kcol + cb * 8;
        cpasync16(sbase + OFF_BHI + rb * ROWB + cb * 16, g_bhi + gi);
        cpasync16(sbase + OFF_BLO + rb * ROWB + cb * 16, g_blo + gi);
    }
}

__global__ void __launch_bounds__(256) k3_mma_kernel(const float* __restrict__ b_o,
                                                     float* __restrict__ out) {
    extern __shared__ char smem[];
    const uint32_t sb = smem_u32(smem);
    const int tid  = threadIdx.x;
    const int lane = tid & 31;
    const int wid  = tid >> 5;
    const int wm   = wid >> 2;       // 0..1
    const int wn   = wid & 3;        // 0..3
    const int row0 = blockIdx.y * BM;
    const int col0 = blockIdx.x * BN;

    float* bias_s = (float*)(smem + 2 * STAGE_B);
    if (tid < 128) bias_s[tid] = b_o[col0 + tid];

    float acc[2][4][4];
#pragma unroll
    for (int mi = 0; mi < 2; mi++)
#pragma unroll
        for (int ni = 0; ni < 4; ni++)
#pragma unroll
            for (int q = 0; q < 4; q++) acc[mi][ni][q] = 0.f;

    const int lrow = lane & 15;
    const int lseg = lane >> 4;
    const uint32_t aoff = (uint32_t)((wm * 32 + lrow) * ROWB + lseg * 16);
    const uint32_t boff = (uint32_t)((wn * 32 + lrow) * ROWB + lseg * 16);

    load_stage(sb, row0, col0, 0, tid);
    CP_COMMIT();

    for (int kt = 0; kt < NKT; kt++) {
        const uint32_t sbuf = sb + (uint32_t)(kt & 1) * STAGE_B;
        if (kt + 1 < NKT) {
            load_stage(sb + (uint32_t)((kt + 1) & 1) * STAGE_B, row0, col0, (kt + 1) * BK, tid);
            CP_COMMIT();
            CP_WAIT1();
        } else {
            CP_WAIT0();
        }
        __syncthreads();

#pragma unroll
        for (int kh = 0; kh < 2; kh++) {
            const uint32_t ko = (uint32_t)(kh * 32);
            uint32_t ah[2][4], al[2][4];
#pragma unroll
            for (int mi = 0; mi < 2; mi++) {
                ldsm4(ah[mi], sbuf + OFF_AHI + aoff + (uint32_t)(mi * 16 * ROWB) + ko);
                ldsm4(al[mi], sbuf + OFF_ALO + aoff + (uint32_t)(mi * 16 * ROWB) + ko);
            }
            uint32_t bh[4][2], bl[4][2];
#pragma unroll
            for (int ng = 0; ng < 2; ng++) {
                uint32_t r[4];
                ldsm4(r, sbuf + OFF_BHI + boff + (uint32_t)(ng * 16 * ROWB) + ko);
                bh[ng * 2 + 0][0] = r[0]; bh[ng * 2 + 0][1] = r[2];
                bh[ng * 2 + 1][0] = r[1]; bh[ng * 2 + 1][1] = r[3];
                ldsm4(r, sbuf + OFF_BLO + boff + (uint32_t)(ng * 16 * ROWB) + ko);
                bl[ng * 2 + 0][0] = r[0]; bl[ng * 2 + 0][1] = r[2];
                bl[ng * 2 + 1][0] = r[1]; bl[ng * 2 + 1][1] = r[3];
            }
#pragma unroll
            for (int mi = 0; mi < 2; mi++) {
#pragma unroll
                for (int ni = 0; ni < 4; ni++) {
                    mma16816(acc[mi][ni], ah[mi], bh[ni]);
                    mma16816(acc[mi][ni], ah[mi], bl[ni]);
                    mma16816(acc[mi][ni], al[mi], bh[ni]);
                }
            }
        }
        __syncthreads();
    }

    const int er = lane >> 2;
    const int ec = (lane & 3) * 2;
#pragma unroll
    for (int mi = 0; mi < 2; mi++) {
#pragma unroll
        for (int ni = 0; ni < 4; ni++) {
            const int row = row0 + wm * 32 + mi * 16 + er;
            const int lc  = wn * 32 + ni * 8 + ec;
            const int col = col0 + lc;
            float2 v0, v1;
            v0.x = acc[mi][ni][0] + bias_s[lc];
            v0.y = acc[mi][ni][1] + bias_s[lc + 1];
            v1.x = acc[mi][ni][2] + bias_s[lc];
            v1.y = acc[mi][ni][3] + bias_s[lc + 1];
            *(float2*)&out[(size_t)row * OUT_ + col] = v0;
            *(float2*)&out[(size_t)(row + 8) * OUT_ + col] = v1;
        }
    }
}

// ============================================================================
// launch
// ============================================================================
extern "C" void kernel_launch(void* const* d_in, const int* in_sizes, int n_in,
                              void* d_out, int out_size) {
    const float* x      = (const float*)d_in[0];
    const float* memory = (const float*)d_in[1];
    const float* W_ar   = (const float*)d_in[2];
    const float* b_ar   = (const float*)d_in[3];
    const float* W_pr   = (const float*)d_in[4];
    const float* b_pr   = (const float*)d_in[5];
    const float* W_f    = (const float*)d_in[6];
    const float* b_f    = (const float*)d_in[7];
    const float* W_r    = (const float*)d_in[8];
    const float* b_r    = (const float*)d_in[9];
    const float* W_o    = (const float*)d_in[10];
    const float* b_o    = (const float*)d_in[11];

    float* out     = (float*)d_out;
    float* new_mem = out + (size_t)BB * OUT_;

    cudaFuncSetAttribute(k2_kernel,     cudaFuncAttributeMaxDynamicSharedMemorySize, K2_SMEM);
    cudaFuncSetAttribute(k3_mma_kernel, cudaFuncAttributeMaxDynamicSharedMemorySize, K3_SMEM);

    pack_kernel<<<(IN_ * NCOLS + 255) / 256, 256>>>(W_ar, W_r, W_f);
    convB_kernel<<<dim3(OUT_ / 32, KTOT / 64), 256>>>(W_o);
    k1_kernel<<<dim3(16, 16), 256>>>(x);
    k2_kernel<<<BB, 256, K2_SMEM>>>(memory, b_ar, W_pr, b_pr, W_f, b_f, W_r, b_r, new_mem);
    convA_kernel<<<(BB * KTOT + 255) / 256, 256>>>(x);
    k3_mma_kernel<<<dim3(OUT_ / BN, BB / BM), 256, K3_SMEM>>>(b_o, out);
}

// round 17
// speedup vs baseline: 1.1420x; 1.1420x over previous
#include <cuda_runtime.h>
#include <cuda_bf16.h>
#include <math.h>
#include <stdint.h>

// Shapes (fixed by the problem)
#define BB     512
#define NSLOT  128
#define IN_    2048
#define MEM_   64
#define OUT_   2048
#define KTOT   2176   // IN + 2*MEM
#define NK1    16     // split-K factor for K1
#define NCOLS  130    // 64 (q) + 65 (xr) + 1 (xf)

// -------------------- device scratch (no allocations allowed) ----------------
__device__ float g_kpart[NK1 * BB * NCOLS];   // K1 partial sums
__device__ float g_wpack[IN_ * NCOLS];        // packed [W_ar | W_r_x | W_f_x]
__device__ float g_ar[BB * MEM_];             // active recall
__device__ float g_pr[BB * MEM_];             // passive recall

// bf16 split operands for tensor-core K3
__device__ __nv_bfloat16 g_ahi[BB * KTOT];      // A = [x | ar | pr] hi
__device__ __nv_bfloat16 g_alo[BB * KTOT];      // A lo
__device__ __nv_bfloat16 g_bhi[OUT_ * KTOT];    // W_o^T hi  (N-major rows, K contiguous)
__device__ __nv_bfloat16 g_blo[OUT_ * KTOT];    // W_o^T lo

// ============================================================================
// PTX helpers (base compute_103 compatible: ldmatrix / mma.sync / cp.async)
// ============================================================================
__device__ __forceinline__ uint32_t smem_u32(const void* p) {
    uint32_t a;
    asm("{ .reg .u64 t; cvta.to.shared.u64 t, %1; cvt.u32.u64 %0, t; }" : "=r"(a) : "l"(p));
    return a;
}

__device__ __forceinline__ void ldsm4(uint32_t* r, uint32_t addr) {
    asm volatile("ldmatrix.sync.aligned.m8n8.x4.shared.b16 {%0,%1,%2,%3}, [%4];"
        : "=r"(r[0]), "=r"(r[1]), "=r"(r[2]), "=r"(r[3]) : "r"(addr));
}

__device__ __forceinline__ void mma16816(float* d, const uint32_t* a, const uint32_t* b) {
    asm volatile("mma.sync.aligned.m16n8k16.row.col.f32.bf16.bf16.f32 "
        "{%0,%1,%2,%3}, {%4,%5,%6,%7}, {%8,%9}, {%0,%1,%2,%3};"
        : "+f"(d[0]), "+f"(d[1]), "+f"(d[2]), "+f"(d[3])
        : "r"(a[0]), "r"(a[1]), "r"(a[2]), "r"(a[3]), "r"(b[0]), "r"(b[1]));
}

__device__ __forceinline__ void cpasync16(uint32_t smem, const void* g) {
    asm volatile("cp.async.cg.shared.global [%0], [%1], 16;" :: "r"(smem), "l"(g));
}
#define CP_COMMIT() asm volatile("cp.async.commit_group;" ::: "memory")
#define CP_WAIT1()  asm volatile("cp.async.wait_group 1;" ::: "memory")
#define CP_WAIT0()  asm volatile("cp.async.wait_group 0;" ::: "memory")

// ============================================================================
// K0: pack the x-side weight columns into one contiguous [2048 x 130] matrix
// ============================================================================
__global__ void pack_kernel(const float* __restrict__ W_ar,
                            const float* __restrict__ W_r,
                            const float* __restrict__ W_f) {
    int idx = blockIdx.x * 256 + threadIdx.x;
    if (idx >= IN_ * NCOLS) return;
    int k = idx / NCOLS;
    int j = idx - k * NCOLS;
    float w;
    if (j < 64)       w = W_ar[k * 64 + j];
    else if (j < 129) w = W_r[k * 65 + (j - 64)];
    else              w = W_f[k];
    g_wpack[idx] = w;
}

// ============================================================================
// K1 v2: partial GEMM  x[512,2048] @ wpack[2048,130] -> g_kpart[16][512][130]
//        grid (16 m-tiles, 16 k-tiles), 256 threads, 16 rows/thread (ILP 16)
// ============================================================================
__global__ void __launch_bounds__(256) k1_kernel(const float* __restrict__ x) {
    const int mb = blockIdx.x;
    const int kb = blockIdx.y;
    const int t  = threadIdx.x;
    __shared__ float xs[32][128];

    for (int i = t; i < 1024; i += 256) {
        int m = i >> 5, c = (i & 31) * 4;
        *(float4*)&xs[m][c] = *(const float4*)&x[(mb * 32 + m) * IN_ + kb * 128 + c];
    }
    __syncthreads();

    const int mh = t >> 7;       // 0/1 -> rows mh*16 .. mh*16+15
    const int j0 = t & 127;
    for (int j = j0; j < NCOLS; j += 128) {
        float acc[16];
#pragma unroll
        for (int m = 0; m < 16; m++) acc[m] = 0.f;
        const float* wp = g_wpack + (kb * 128) * NCOLS + j;
#pragma unroll 8
        for (int k = 0; k < 128; k++) {
            float w = wp[k * NCOLS];
#pragma unroll
            for (int m = 0; m < 16; m++) acc[m] = fmaf(xs[mh * 16 + m][k], w, acc[m]);
        }
        float* outp = g_kpart + (kb * BB + mb * 32 + mh * 16) * NCOLS + j;
#pragma unroll
        for (int m = 0; m < 16; m++) outp[m * NCOLS] = acc[m];
    }
}

// ============================================================================
// K2 v3: per-batch fused attention/softmax/recalls + gated memory update.
//        256 threads. Update is a register-tiled GEMM (thread = 4 slots x
//        8 cols), epilogue streams straight to global. Warps 4-7 compute
//        forget/r64 concurrently with warps 0-3's logits.
// ============================================================================
#define K2_SMEM ((NSLOT * 65 + 64 * 68) * 4)   // 50688 bytes dynamic

__global__ void __launch_bounds__(256) k2_kernel(
        const float* __restrict__ memory,
        const float* __restrict__ b_ar,
        const float* __restrict__ W_pr,
        const float* __restrict__ b_pr,
        const float* __restrict__ W_f,
        const float* __restrict__ b_f,
        const float* __restrict__ W_r,
        const float* __restrict__ b_r,
        float* __restrict__ new_memory) {
    extern __shared__ float dyn[];
    float* mem_s = dyn;                       // [128][65]
    float* wrm   = dyn + NSLOT * 65;          // [64][68] (cols 0..64 valid)

    __shared__ float sq[64];
    __shared__ float sxr[65];
    __shared__ float swfm[64];
    __shared__ float swpr[64];
    __shared__ float sscore[128];
    __shared__ float sp[128];
    __shared__ float sfgt[128];
    __shared__ float sr64[128];
    __shared__ float red[256];
    __shared__ float wred[4][8];
    __shared__ float sxf;

    const int b    = blockIdx.x;
    const int t    = threadIdx.x;
    const int lane = t & 31;
    const int wid  = t >> 5;

    // ---- reduce K1 split-K partials, add biases (130 cols, one pass) ----
    if (t < NCOLS) {
        float s = 0.f;
#pragma unroll
        for (int kb = 0; kb < NK1; kb++) s += g_kpart[(kb * BB + b) * NCOLS + t];
        if (t < 64)       sq[t] = s + b_ar[t];
        else if (t < 129) sxr[t - 64] = s + b_r[t - 64];
        else              sxf = s + b_f[0];
    }

    // ---- stage weights ----
    for (int i = t; i < 64 * 68; i += 256) {
        int k = i / 68, c = i - k * 68;
        wrm[i] = (c < 65) ? W_r[IN_ * 65 + k * 65 + c] : 0.f;
    }
    if (t < 64) { swfm[t] = W_f[IN_ + t]; swpr[t] = W_pr[t]; }

    // ---- stage memory[b] (float4 loads, padded stride-65 rows) ----
    const float4* m4 = (const float4*)(memory + (size_t)b * (NSLOT * MEM_));
    for (int i = t; i < 2048; i += 256) {
        int row = i >> 4, c4 = (i & 15) * 4;
        float4 v = m4[i];
        float* d = &mem_s[row * 65 + c4];
        d[0] = v.x; d[1] = v.y; d[2] = v.z; d[3] = v.w;
    }
    __syncthreads();                                          // (1)

    // ---- split work: warps 0-3 logits; warps 4-7 forget/r64 ----
    float sc = 0.f, pl = 0.f;
    if (t < 128) {
        const float* my = mem_s + t * 65;
        float s0 = 0.f, s1 = 0.f, p0 = 0.f, p1 = 0.f;
#pragma unroll
        for (int k = 0; k < 64; k += 2) {
            float m0 = my[k], m1 = my[k + 1];
            s0 = fmaf(m0, sq[k], s0);
            s1 = fmaf(m1, sq[k + 1], s1);
            p0 = fmaf(m0, swpr[k], p0);
            p1 = fmaf(m1, swpr[k + 1], p1);
        }
        sc = s0 + s1;
        pl = p0 + p1 + b_pr[0];
    } else {
        const int s = t - 128;
        const float* my = mem_s + s * 65;
        float f0 = 0.f, f1 = 0.f, r0 = 0.f, r1 = 0.f;
#pragma unroll
        for (int k = 0; k < 64; k += 2) {
            float m0 = my[k], m1 = my[k + 1];
            f0 = fmaf(m0, swfm[k], f0);
            f1 = fmaf(m1, swfm[k + 1], f1);
            r0 = fmaf(m0, wrm[k * 68 + 64], r0);
            r1 = fmaf(m1, wrm[(k + 1) * 68 + 64], r1);
        }
        sfgt[s] = 1.1f / (1.f + expf(-(f0 + f1 + sxf)));
        sr64[s] = r0 + r1 + sxr[64];
    }

    // ---- softmax 1 (active): max then sum, shuffle + 8-way combine ----
    float v = (t < 128) ? sc : -INFINITY;
#pragma unroll
    for (int o = 16; o > 0; o >>= 1) v = fmaxf(v, __shfl_xor_sync(0xFFFFFFFFu, v, o));
    if (lane == 0) wred[0][wid] = v;
    __syncthreads();                                          // (2)
    float mx = fmaxf(fmaxf(wred[0][0], wred[0][1]), fmaxf(wred[0][2], wred[0][3]));
    float e1 = (t < 128) ? expf(sc - mx) : 0.f;
    v = e1;
#pragma unroll
    for (int o = 16; o > 0; o >>= 1) v += __shfl_xor_sync(0xFFFFFFFFu, v, o);
    if (lane == 0) wred[1][wid] = v;

    // ---- softmax 2 (passive) ----
    v = (t < 128) ? pl : -INFINITY;
#pragma unroll
    for (int o = 16; o > 0; o >>= 1) v = fmaxf(v, __shfl_xor_sync(0xFFFFFFFFu, v, o));
    if (lane == 0) wred[2][wid] = v;
    __syncthreads();                                          // (3)
    float s1t = wred[1][0] + wred[1][1] + wred[1][2] + wred[1][3];
    if (t < 128) sscore[t] = e1 / s1t;
    float mx2 = fmaxf(fmaxf(wred[2][0], wred[2][1]), fmaxf(wred[2][2], wred[2][3]));
    float e2 = (t < 128) ? expf(pl - mx2) : 0.f;
    v = e2;
#pragma unroll
    for (int o = 16; o > 0; o >>= 1) v += __shfl_xor_sync(0xFFFFFFFFu, v, o);
    if (lane == 0) wred[3][wid] = v;
    __syncthreads();                                          // (4)
    float s2t = wred[3][0] + wred[3][1] + wred[3][2] + wred[3][3];
    if (t < 128) sp[t] = e2 / s2t;
    __syncthreads();                                          // (5)

    // ---- active / passive recall: col = t&63, 4-way row split ----
    {
        const int c = t & 63;
        const int h = t >> 6;               // 0..3 -> rows h*32..h*32+31
        float a = 0.f, p = 0.f;
#pragma unroll 4
        for (int n = h * 32; n < h * 32 + 32; n++) {
            float mv = mem_s[n * 65 + c];
            a = fmaf(mv, sscore[n], a);
            p = fmaf(mv, sp[n], p);
        }
        red[t] = a;
        __syncthreads();                                      // (6)
        if (t < 64) g_ar[b * 64 + t] = red[t] + red[t + 64] + red[t + 128] + red[t + 192];
        __syncthreads();                                      // (7)
        red[t] = p;
        __syncthreads();                                      // (8)
        if (t < 64) g_pr[b * 64 + t] = red[t] + red[t + 64] + red[t + 128] + red[t + 192];
    }

    // ---- gated memory update: register-tiled GEMM, 4 slots x 8 cols/thread --
    const int tr = t >> 3;          // 0..31  -> slots tr*4 .. tr*4+3
    const int tc = t & 7;           // 0..7   -> cols  tc*8 .. tc*8+7
    const int s0 = tr * 4;
    float acc[4][8];
#pragma unroll
    for (int i = 0; i < 4; i++)
#pragma unroll
        for (int j = 0; j < 8; j++) acc[i][j] = 0.f;

#pragma unroll 4
    for (int k = 0; k < 64; k++) {
        float4 w0 = *(const float4*)&wrm[k * 68 + tc * 8];
        float4 w1 = *(const float4*)&wrm[k * 68 + tc * 8 + 4];
        float m0 = mem_s[(s0 + 0) * 65 + k];
        float m1 = mem_s[(s0 + 1) * 65 + k];
        float m2 = mem_s[(s0 + 2) * 65 + k];
        float m3 = mem_s[(s0 + 3) * 65 + k];
#pragma unroll
        for (int i = 0; i < 4; i++) {
            float mv = (i == 0) ? m0 : (i == 1) ? m1 : (i == 2) ? m2 : m3;
            acc[i][0] = fmaf(mv, w0.x, acc[i][0]);
            acc[i][1] = fmaf(mv, w0.y, acc[i][1]);
            acc[i][2] = fmaf(mv, w0.z, acc[i][2]);
            acc[i][3] = fmaf(mv, w0.w, acc[i][3]);
            acc[i][4] = fmaf(mv, w1.x, acc[i][4]);
            acc[i][5] = fmaf(mv, w1.y, acc[i][5]);
            acc[i][6] = fmaf(mv, w1.z, acc[i][6]);
            acc[i][7] = fmaf(mv, w1.w, acc[i][7]);
        }
    }

    // epilogue: new_mem = mem*fgt + r64*(acc + sxr), straight to global
    float* orow = new_memory + (size_t)b * (NSLOT * MEM_);
#pragma unroll
    for (int i = 0; i < 4; i++) {
        const int s = s0 + i;
        const float fg = sfgt[s];
        const float r6 = sr64[s];
        const float* ms = &mem_s[s * 65 + tc * 8];
        float4 o0, o1;
        o0.x = fmaf(ms[0], fg, r6 * (acc[i][0] + sxr[tc * 8 + 0]));
        o0.y = fmaf(ms[1], fg, r6 * (acc[i][1] + sxr[tc * 8 + 1]));
        o0.z = fmaf(ms[2], fg, r6 * (acc[i][2] + sxr[tc * 8 + 2]));
        o0.w = fmaf(ms[3], fg, r6 * (acc[i][3] + sxr[tc * 8 + 3]));
        o1.x = fmaf(ms[4], fg, r6 * (acc[i][4] + sxr[tc * 8 + 4]));
        o1.y = fmaf(ms[5], fg, r6 * (acc[i][5] + sxr[tc * 8 + 5]));
        o1.z = fmaf(ms[6], fg, r6 * (acc[i][6] + sxr[tc * 8 + 6]));
        o1.w = fmaf(ms[7], fg, r6 * (acc[i][7] + sxr[tc * 8 + 7]));
        *(float4*)&orow[s * 64 + tc * 8]     = o0;
        *(float4*)&orow[s * 64 + tc * 8 + 4] = o1;
    }
}

// ============================================================================
// convA: build bf16 hi/lo of A = [x | ar | pr]  (512 x 2176)
// ============================================================================
__global__ void convA_kernel(const float* __restrict__ x) {
    int i = blockIdx.x * 256 + threadIdx.x;
    if (i >= BB * KTOT) return;
    int m = i / KTOT, k = i - m * KTOT;
    float v;
    if (k < IN_)              v = x[m * IN_ + k];
    else if (k < IN_ + MEM_)  v = g_ar[m * MEM_ + (k - IN_)];
    else                      v = g_pr[m * MEM_ + (k - IN_ - MEM_)];
    __nv_bfloat16 h = __float2bfloat16(v);
    g_ahi[i] = h;
    g_alo[i] = __float2bfloat16(v - __bfloat162float(h));
}

// ============================================================================
// convB v2: transpose + bf16 split of W_o with packed uint32 stores.
//           block tile: 64 k rows x 32 n cols.  grid (64, 34), 256 threads.
// ============================================================================
__global__ void __launch_bounds__(256) convB_kernel(const float* __restrict__ W_o) {
    __shared__ float tsm[64][33];
    const int nb = blockIdx.x;   // 64 n-tiles of 32
    const int kb = blockIdx.y;   // 34 k-tiles of 64
    const int tx = threadIdx.x & 31, ty = threadIdx.x >> 5;

    for (int r = ty; r < 64; r += 8)
        tsm[r][tx] = W_o[(size_t)(kb * 64 + r) * OUT_ + nb * 32 + tx];
    __syncthreads();

#pragma unroll
    for (int it = 0; it < 4; it++) {
        int n  = it * 8 + ty;   // 0..31 (local n)
        int kp = tx;            // 0..31 (k pair)
        float v0 = tsm[kp * 2][n];
        float v1 = tsm[kp * 2 + 1][n];
        __nv_bfloat16 h0 = __float2bfloat16(v0);
        __nv_bfloat16 h1 = __float2bfloat16(v1);
        __nv_bfloat16 l0 = __float2bfloat16(v0 - __bfloat162float(h0));
        __nv_bfloat16 l1 = __float2bfloat16(v1 - __bfloat162float(h1));
        uint32_t uh = ((uint32_t)__bfloat16_as_ushort(h1) << 16) | __bfloat16_as_ushort(h0);
        uint32_t ul = ((uint32_t)__bfloat16_as_ushort(l1) << 16) | __bfloat16_as_ushort(l0);
        size_t o2 = ((size_t)(nb * 32 + n) * KTOT + kb * 64) / 2 + kp;
        ((uint32_t*)g_bhi)[o2] = uh;
        ((uint32_t*)g_blo)[o2] = ul;
    }
}

// ============================================================================
// K3: mma.sync bf16 3-split GEMM  D[512,2048] = A[512,2176] @ W_o + b_o
//     CTA tile 64(M) x 128(N), BK=32, 8 warps (warp tile 32x32),
//     cp.async double-buffered SMEM (rows padded to 80B: conflict-free LDSM).
// ============================================================================
#define BM     64
#define BN     128
#define BK     32
#define ROWB   80                       // 64B data + 16B pad per BK row
#define OFF_AHI 0
#define OFF_ALO (BM * ROWB)             // 5120
#define OFF_BHI (2 * BM * ROWB)         // 10240
#define OFF_BLO (OFF_BHI + BN * ROWB)   // 20480
#define STAGE_B (OFF_BLO + BN * ROWB)   // 30720
#define NKT    (KTOT / BK)              // 68
#define K3_SMEM (2 * STAGE_B + 512)

__device__ __forceinline__ void load_stage(uint32_t sbase, int row0, int col0,
                                           int kcol, int tid) {
    const int r = tid >> 2, c = tid & 3;
    {
        size_t gi = (size_t)(row0 + r) * KTOT + kcol + c * 8;
        cpasync16(sbase + OFF_AHI + r * ROWB + c * 16, g_ahi + gi);
        cpasync16(sbase + OFF_ALO + r * ROWB + c * 16, g_alo + gi);
    }
#pragma unroll
    for (int it = 0; it < 2; it++) {
        int i = tid + it * 256;
        int rb = i >> 2, cb = i & 3;
        size_t gi = (size_t)(col0 + rb) * KTOT + kcol + cb * 8;
        cpasync16(sbase + OFF_BHI + rb * ROWB + cb * 16, g_bhi + gi);
        cpasync16(sbase + OFF_BLO + rb * ROWB + cb * 16, g_blo + gi);
    }
}

__global__ void __launch_bounds__(256) k3_mma_kernel(const float* __restrict__ b_o,
                                                     float* __restrict__ out) {
    extern __shared__ char smem[];
    const uint32_t sb = smem_u32(smem);
    const int tid  = threadIdx.x;
    const int lane = tid & 31;
    const int wid  = tid >> 5;
    const int wm   = wid >> 2;       // 0..1
    const int wn   = wid & 3;        // 0..3
    const int row0 = blockIdx.y * BM;
    const int col0 = blockIdx.x * BN;

    float* bias_s = (float*)(smem + 2 * STAGE_B);
    if (tid < 128) bias_s[tid] = b_o[col0 + tid];

    float acc[2][4][4];
#pragma unroll
    for (int mi = 0; mi < 2; mi++)
#pragma unroll
        for (int ni = 0; ni < 4; ni++)
#pragma unroll
            for (int q = 0; q < 4; q++) acc[mi][ni][q] = 0.f;

    const int lrow = lane & 15;
    const int lseg = lane >> 4;
    const uint32_t aoff = (uint32_t)((wm * 32 + lrow) * ROWB + lseg * 16);
    const uint32_t boff = (uint32_t)((wn * 32 + lrow) * ROWB + lseg * 16);

    load_stage(sb, row0, col0, 0, tid);
    CP_COMMIT();

    for (int kt = 0; kt < NKT; kt++) {
        const uint32_t sbuf = sb + (uint32_t)(kt & 1) * STAGE_B;
        if (kt + 1 < NKT) {
            load_stage(sb + (uint32_t)((kt + 1) & 1) * STAGE_B, row0, col0, (kt + 1) * BK, tid);
            CP_COMMIT();
            CP_WAIT1();
        } else {
            CP_WAIT0();
        }
        __syncthreads();

#pragma unroll
        for (int kh = 0; kh < 2; kh++) {
            const uint32_t ko = (uint32_t)(kh * 32);
            uint32_t ah[2][4], al[2][4];
#pragma unroll
            for (int mi = 0; mi < 2; mi++) {
                ldsm4(ah[mi], sbuf + OFF_AHI + aoff + (uint32_t)(mi * 16 * ROWB) + ko);
                ldsm4(al[mi], sbuf + OFF_ALO + aoff + (uint32_t)(mi * 16 * ROWB) + ko);
            }
            uint32_t bh[4][2], bl[4][2];
#pragma unroll
            for (int ng = 0; ng < 2; ng++) {
                uint32_t r[4];
                ldsm4(r, sbuf + OFF_BHI + boff + (uint32_t)(ng * 16 * ROWB) + ko);
                bh[ng * 2 + 0][0] = r[0]; bh[ng * 2 + 0][1] = r[2];
                bh[ng * 2 + 1][0] = r[1]; bh[ng * 2 + 1][1] = r[3];
                ldsm4(r, sbuf + OFF_BLO + boff + (uint32_t)(ng * 16 * ROWB) + ko);
                bl[ng * 2 + 0][0] = r[0]; bl[ng * 2 + 0][1] = r[2];
                bl[ng * 2 + 1][0] = r[1]; bl[ng * 2 + 1][1] = r[3];
            }
#pragma unroll
            for (int mi = 0; mi < 2; mi++) {
#pragma unroll
                for (int ni = 0; ni < 4; ni++) {
                    mma16816(acc[mi][ni], ah[mi], bh[ni]);
                    mma16816(acc[mi][ni], ah[mi], bl[ni]);
                    mma16816(acc[mi][ni], al[mi], bh[ni]);
                }
            }
        }
        __syncthreads();
    }

    const int er = lane >> 2;
    const int ec = (lane & 3) * 2;
#pragma unroll
    for (int mi = 0; mi < 2; mi++) {
#pragma unroll
        for (int ni = 0; ni < 4; ni++) {
            const int row = row0 + wm * 32 + mi * 16 + er;
            const int lc  = wn * 32 + ni * 8 + ec;
            const int col = col0 + lc;
            float2 v0, v1;
            v0.x = acc[mi][ni][0] + bias_s[lc];
            v0.y = acc[mi][ni][1] + bias_s[lc + 1];
            v1.x = acc[mi][ni][2] + bias_s[lc];
            v1.y = acc[mi][ni][3] + bias_s[lc + 1];
            *(float2*)&out[(size_t)row * OUT_ + col] = v0;
            *(float2*)&out[(size_t)(row + 8) * OUT_ + col] = v1;
        }
    }
}

// ============================================================================
// launch
// ============================================================================
extern "C" void kernel_launch(void* const* d_in, const int* in_sizes, int n_in,
                              void* d_out, int out_size) {
    const float* x      = (const float*)d_in[0];
    const float* memory = (const float*)d_in[1];
    const float* W_ar   = (const float*)d_in[2];
    const float* b_ar   = (const float*)d_in[3];
    const float* W_pr   = (const float*)d_in[4];
    const float* b_pr   = (const float*)d_in[5];
    const float* W_f    = (const float*)d_in[6];
    const float* b_f    = (const float*)d_in[7];
    const float* W_r    = (const float*)d_in[8];
    const float* b_r    = (const float*)d_in[9];
    const float* W_o    = (const float*)d_in[10];
    const float* b_o    = (const float*)d_in[11];

    float* out     = (float*)d_out;
    float* new_mem = out + (size_t)BB * OUT_;

    cudaFuncSetAttribute(k2_kernel,     cudaFuncAttributeMaxDynamicSharedMemorySize, K2_SMEM);
    cudaFuncSetAttribute(k3_mma_kernel, cudaFuncAttributeMaxDynamicSharedMemorySize, K3_SMEM);

    pack_kernel<<<(IN_ * NCOLS + 255) / 256, 256>>>(W_ar, W_r, W_f);
    convB_kernel<<<dim3(OUT_ / 32, KTOT / 64), 256>>>(W_o);
    k1_kernel<<<dim3(16, 16), 256>>>(x);
    k2_kernel<<<BB, 256, K2_SMEM>>>(memory, b_ar, W_pr, b_pr, W_f, b_f, W_r, b_r, new_mem);
    convA_kernel<<<(BB * KTOT + 255) / 256, 256>>>(x);
    k3_mma_kernel<<<dim3(OUT_ / BN, BB / BM), 256, K3_SMEM>>>(b_o, out);
}